// round 9
// baseline (speedup 1.0000x reference)
#include <cuda_runtime.h>
#include <math.h>
#include <stdint.h>

#define T_FRAMES 2048
#define EPROJS   1024
#define DUNITS   512
#define JOINT    512
#define ODIM     10000
#define NB       148
#define NT       512
#define NWARP    (NT / 32)

// ---------------- global scratch ----------------
__device__ float g_hp[T_FRAMES * JOINT];     // encoder-side joint projection

struct __align__(128) Slot16  { float4 v;   float pad[28]; };
struct __align__(128) TagSlot { float4 pay; float tag; float pad[27]; };

__device__ Slot16  g_pslot[2][NB];           // per-block partial (m, s, a-bits, tag)
__device__ TagSlot g_yslot[NB];              // per-block y chunk + epoch tag
__device__ TagSlot g_dvslot[NB];             // per-block dv chunk + epoch tag
__device__ float4  g_ybc[DUNITS / 4];        // assembled y broadcast (block0 writes)
__device__ float4  g_dvbc[JOINT / 4];        // assembled dv broadcast
__device__ Slot16  g_rp;                     // final result (pred-bits, logp, tag, _)
__device__ __align__(128) float g_ry;        // y broadcast ready tag
__device__ __align__(128) float g_rdv;       // dv broadcast ready tag

__device__ __forceinline__ float4 ldvol_f4(const float4* p) {
    float4 v;
    asm volatile("ld.volatile.global.v4.f32 {%0,%1,%2,%3}, [%4];"
                 : "=f"(v.x), "=f"(v.y), "=f"(v.z), "=f"(v.w) : "l"(p));
    return v;
}
__device__ __forceinline__ void stvol_f4(float4* p, float4 v) {
    asm volatile("st.volatile.global.v4.f32 [%0], {%1,%2,%3,%4};"
                 :: "l"(p), "f"(v.x), "f"(v.y), "f"(v.z), "f"(v.w));
}
__device__ __forceinline__ float ld_acquire_f32(const float* p) {
    float v;
    asm volatile("ld.acquire.gpu.global.f32 %0, [%1];" : "=f"(v) : "l"(p) : "memory");
    return v;
}
__device__ __forceinline__ void st_release_f32(float* p, float v) {
    asm volatile("st.release.gpu.global.f32 [%0], %1;" :: "l"(p), "f"(v) : "memory");
}
__device__ __forceinline__ float sigm(float x) { return 1.f / (1.f + expf(-x)); }

// ---------------- hp = h @ W_enc^T + b_enc ----------------
__global__ void hp_kernel(const float* __restrict__ h,
                          const float* __restrict__ Wenc,
                          const float* __restrict__ benc) {
    __shared__ float sh[8 * EPROJS];
    const int tid  = threadIdx.x;
    const int warp = tid >> 5;
    const int lane = tid & 31;
    const size_t t0 = (size_t)blockIdx.x * 8;

    const float4* hsrc = (const float4*)(h + t0 * EPROJS);
    float4* sh4 = (float4*)sh;
    for (int i = tid; i < 8 * EPROJS / 4; i += 256) sh4[i] = hsrc[i];
    __syncthreads();

    const float4* w0 = (const float4*)Wenc;
    for (int pass = 0; pass < 16; pass++) {
        int jb = (pass * 8 + warp) * 4;
        float acc[8][4];
#pragma unroll
        for (int tt = 0; tt < 8; tt++)
#pragma unroll
            for (int jj = 0; jj < 4; jj++) acc[tt][jj] = 0.f;

        for (int qq = 0; qq < 8; qq++) {
            int q = qq * 32 + lane;
            float4 w[4];
#pragma unroll
            for (int jj = 0; jj < 4; jj++)
                w[jj] = w0[(size_t)(jb + jj) * (EPROJS / 4) + q];
#pragma unroll
            for (int tt = 0; tt < 8; tt++) {
                float4 hv = sh4[tt * (EPROJS / 4) + q];
#pragma unroll
                for (int jj = 0; jj < 4; jj++)
                    acc[tt][jj] += hv.x * w[jj].x + hv.y * w[jj].y +
                                   hv.z * w[jj].z + hv.w * w[jj].w;
            }
        }
#pragma unroll
        for (int tt = 0; tt < 8; tt++) {
#pragma unroll
            for (int jj = 0; jj < 4; jj++) {
                float v = acc[tt][jj];
                for (int off = 16; off; off >>= 1)
                    v += __shfl_down_sync(0xffffffffu, v, off);
                if (lane == 0)
                    g_hp[(t0 + tt) * JOINT + jb + jj] = v + benc[jb + jj];
            }
        }
    }
}

// ---------------- smem layout (floats) ----------------
#define SM_WOUT   0
#define SM_WHH    (SM_WOUT + 68 * JOINT)
#define SM_WIH    (SM_WHH + 16 * DUNITS)
#define SM_WDEC   (SM_WIH + 16 * DUNITS)
#define SM_Y      (SM_WDEC + 4 * DUNITS)
#define SM_DV     (SM_Y + DUNITS)
#define SM_Z      (SM_DV + JOINT)          /* reused as ey during LSTM */
#define SM_HP     (SM_Z + JOINT)
#define SM_BO     (SM_HP + JOINT)
#define SM_BS     (SM_BO + 68)
#define SM_GH     (SM_BS + 16)
#define SM_GT     (SM_GH + 16)
#define SM_C      (SM_GT + 16)
#define SM_BC     (SM_C + 4)
#define SM_WM     (SM_BC + 4)
#define SM_WA     (SM_WM + NWARP)
#define SM_WS     (SM_WA + NWARP)
#define SM_PM     (SM_WS + NWARP)
#define SM_PS     (SM_PM + NB)
#define SM_PA     (SM_PS + NB)
#define SM_TOTAL_FLOATS (SM_PA + NB)

__global__ void __launch_bounds__(NT, 1)
decode_kernel(const float* __restrict__ embed,
              const float* __restrict__ Wih, const float* __restrict__ Whh,
              const float* __restrict__ bih, const float* __restrict__ bhh,
              const float* __restrict__ Wdec, const float* __restrict__ Wout,
              const float* __restrict__ bout,
              float* __restrict__ out, int out_size) {
    extern __shared__ float sm[];
    const int b    = blockIdx.x;
    const int tid  = threadIdx.x;
    const int warp = tid >> 5;
    const int lane = tid & 31;

    const int r0 = (b * ODIM) / NB, r1 = ((b + 1) * ODIM) / NB, nr = r1 - r0;
    const int k0 = (b * DUNITS) / NB, k1 = ((b + 1) * DUNITS) / NB, nk = k1 - k0;

    // block0 slot-poll mapping (tid < NB)
    const int ps  = tid;
    const int pk0 = (ps < NB) ? (ps * DUNITS) / NB : 0;
    const int pk1 = (ps < NB) ? ((ps + 1) * DUNITS) / NB : 0;
    const int pnk = pk1 - pk0;

    float* sWout = sm + SM_WOUT;
    float* sWhh  = sm + SM_WHH;
    float* sWih  = sm + SM_WIH;
    float* sWdec = sm + SM_WDEC;
    float* s_y   = sm + SM_Y;
    float* s_dv  = sm + SM_DV;
    float* s_z   = sm + SM_Z;
    float* s_hp  = sm + SM_HP;
    float* s_bo  = sm + SM_BO;
    float* s_bs  = sm + SM_BS;
    float* s_gh  = sm + SM_GH;
    float* s_gt  = sm + SM_GT;
    float* s_c   = sm + SM_C;
    float* s_bc  = sm + SM_BC;
    float* s_wm  = sm + SM_WM;
    int*   s_wa  = (int*)(sm + SM_WA);
    float* s_ws  = sm + SM_WS;
    float* s_pm  = sm + SM_PM;
    float* s_ps  = sm + SM_PS;
    int*   s_pa  = (int*)(sm + SM_PA);

    // ---- load weights into shared (resident for entire decode) ----
    {
        const float4* src = (const float4*)(Wout + (size_t)r0 * JOINT);
        float4* dst = (float4*)sWout;
        for (int i = tid; i < nr * (JOINT / 4); i += NT) dst[i] = src[i];
    }
    for (int i = tid; i < nr; i += NT) s_bo[i] = bout[r0 + i];
    {
        const int ng = 4 * nk;
        for (int i = tid; i < ng * (DUNITS / 4); i += NT) {
            int lr = i / (DUNITS / 4), x = i % (DUNITS / 4);
            int gi = lr & 3, ki = lr >> 2;
            size_t G = (size_t)(gi * DUNITS + k0 + ki);
            ((float4*)sWhh)[i] = ((const float4*)(Whh + G * DUNITS))[x];
            ((float4*)sWih)[i] = ((const float4*)(Wih + G * DUNITS))[x];
        }
        for (int i = tid; i < ng; i += NT) {
            int gi = i & 3, ki = i >> 2;
            int G = gi * DUNITS + k0 + ki;
            s_bs[i] = bih[G] + bhh[G];
        }
    }
    {
        const float4* src = (const float4*)(Wdec + (size_t)k0 * DUNITS);
        float4* dst = (float4*)sWdec;
        for (int i = tid; i < nk * (DUNITS / 4); i += NT) dst[i] = src[i];
    }
    __syncthreads();

    float e = 1.0f;   // emission epoch tag (prologue = 1)

    // ================= prologue: y0 + broadcast =================
    if (warp == 0) {
        float yv = 0.f;
        if (lane < nk) {
            float gi_ = s_bs[4 * lane + 0];
            float gg_ = s_bs[4 * lane + 2];
            float go_ = s_bs[4 * lane + 3];
            float c  = sigm(gi_) * tanhf(gg_);
            yv = sigm(go_) * tanhf(c);
            s_c[lane] = c;
        }
        float y0 = __shfl_sync(0xffffffffu, yv, 0);
        float y1 = __shfl_sync(0xffffffffu, yv, 1);
        float y2 = __shfl_sync(0xffffffffu, yv, 2);
        float y3 = __shfl_sync(0xffffffffu, yv, 3);
        if (lane == 0) {
            stvol_f4(&g_yslot[b].pay, make_float4(y0, y1, y2, y3));
            st_release_f32(&g_yslot[b].tag, e);
        }
    }
    if (b == 0) {
        if (ps < NB) {
            while (ld_acquire_f32(&g_yslot[ps].tag) != e) {}
            float4 p = ldvol_f4(&g_yslot[ps].pay);
            s_y[pk0] = p.x;
            if (pnk > 1) s_y[pk0 + 1] = p.y;
            if (pnk > 2) s_y[pk0 + 2] = p.z;
            if (pnk > 3) s_y[pk0 + 3] = p.w;
        }
        __syncthreads();
        if (tid < DUNITS / 4) stvol_f4(&g_ybc[tid], ((const float4*)s_y)[tid]);
        __syncthreads();
        if (tid == 0) st_release_f32(&g_ry, e);
    } else {
        if (tid == 0) { while (ld_acquire_f32(&g_ry) != e) {} }
        __syncthreads();
        if (tid < DUNITS / 4) ((float4*)s_y)[tid] = __ldcv(&g_ybc[tid]);
        __syncthreads();
    }

    // dv chunk (warp0) -------------------------------------------------------
    if (warp == 0) {
        float dvp[4] = {0.f, 0.f, 0.f, 0.f};
#pragma unroll 4
        for (int r = 0; r < 4; r++) {
            if (r < nk) {
                const float4* r4 = (const float4*)(sWdec + r * DUNITS);
                const float4* y4 = (const float4*)s_y;
                float a = 0.f;
#pragma unroll
                for (int q = 0; q < 4; q++) {
                    float4 w = r4[lane + 32 * q], yv = y4[lane + 32 * q];
                    a += w.x * yv.x + w.y * yv.y + w.z * yv.z + w.w * yv.w;
                }
                for (int off = 16; off; off >>= 1)
                    a += __shfl_down_sync(0xffffffffu, a, off);
                dvp[r] = a;
            }
        }
        if (lane == 0) {
            stvol_f4(&g_dvslot[b].pay, make_float4(dvp[0], dvp[1], dvp[2], dvp[3]));
            st_release_f32(&g_dvslot[b].tag, e);
        }
    }
    // gh rows + dv assemble
    if (b == 0) {
        if (warp >= 5) {
            for (int g = warp - 5; g < 4 * nk; g += (NWARP - 5)) {
                const float4* r4 = (const float4*)(sWhh + g * DUNITS);
                const float4* y4 = (const float4*)s_y;
                float a = 0.f;
#pragma unroll
                for (int q = 0; q < 4; q++) {
                    float4 w = r4[lane + 32 * q], yv = y4[lane + 32 * q];
                    a += w.x * yv.x + w.y * yv.y + w.z * yv.z + w.w * yv.w;
                }
                for (int off = 16; off; off >>= 1)
                    a += __shfl_down_sync(0xffffffffu, a, off);
                if (lane == 0) s_gh[g] = a;
            }
        } else if (ps < NB) {
            while (ld_acquire_f32(&g_dvslot[ps].tag) != e) {}
            float4 p = ldvol_f4(&g_dvslot[ps].pay);
            s_dv[pk0] = p.x;
            if (pnk > 1) s_dv[pk0 + 1] = p.y;
            if (pnk > 2) s_dv[pk0 + 2] = p.z;
            if (pnk > 3) s_dv[pk0 + 3] = p.w;
        }
        __syncthreads();
        if (tid < JOINT / 4) stvol_f4(&g_dvbc[tid], ((const float4*)s_dv)[tid]);
        __syncthreads();
        if (tid == 0) st_release_f32(&g_rdv, e);
    } else {
        if (warp >= 1) {
            for (int g = warp - 1; g < 4 * nk; g += (NWARP - 1)) {
                const float4* r4 = (const float4*)(sWhh + g * DUNITS);
                const float4* y4 = (const float4*)s_y;
                float a = 0.f;
#pragma unroll
                for (int q = 0; q < 4; q++) {
                    float4 w = r4[lane + 32 * q], yv = y4[lane + 32 * q];
                    a += w.x * yv.x + w.y * yv.y + w.z * yv.z + w.w * yv.w;
                }
                for (int off = 16; off; off >>= 1)
                    a += __shfl_down_sync(0xffffffffu, a, off);
                if (lane == 0) s_gh[g] = a;
            }
        }
        if (tid == 0) { while (ld_acquire_f32(&g_rdv) != e) {} }
        __syncthreads();
        if (tid < JOINT / 4) ((float4*)s_dv)[tid] = __ldcv(&g_dvbc[tid]);
        __syncthreads();
    }
    s_hp[tid] = g_hp[tid];   // hp row 0
    __syncthreads();

    float score = 0.f;

    for (int t = 0; t < T_FRAMES; t++) {
        const int par = t & 1;
        const float ttag = (float)(t + 1);

        // ===== z fully local =====
        s_z[tid] = tanhf(s_hp[tid] + s_dv[tid]);
        __syncthreads();

        float4 zr[4];
#pragma unroll
        for (int q = 0; q < 4; q++) zr[q] = ((const float4*)s_z)[lane + 32 * q];

        float hpn = (t + 1 < T_FRAMES)
                        ? __ldg(&g_hp[(size_t)(t + 1) * JOINT + tid]) : 0.f;

        // ===== logits rows =====
        float accv[5];
        int rcount = 0;
        for (int lr = warp, i = 0; lr < nr; lr += NWARP, i++) {
            const float4* r4 = (const float4*)(sWout + lr * JOINT);
            float a = 0.f;
#pragma unroll
            for (int q = 0; q < 4; q++) {
                float4 w = r4[lane + 32 * q];
                a += w.x * zr[q].x + w.y * zr[q].y + w.z * zr[q].z + w.w * zr[q].w;
            }
            accv[i] = a;
            rcount = i + 1;
        }
        s_hp[tid] = hpn;
#pragma unroll
        for (int i = 0; i < 5; i++) {
            float a = (i < rcount) ? accv[i] : 0.f;
            a += __shfl_down_sync(0xffffffffu, a, 16);
            a += __shfl_down_sync(0xffffffffu, a, 8);
            a += __shfl_down_sync(0xffffffffu, a, 4);
            a += __shfl_down_sync(0xffffffffu, a, 2);
            a += __shfl_down_sync(0xffffffffu, a, 1);
            accv[i] = a;
        }

        if (lane == 0) {
            float m = -INFINITY, s = 0.f;
            int a = 0x7fffffff;
#pragma unroll
            for (int i = 0; i < 5; i++) {
                if (i < rcount) {
                    int lr = warp + NWARP * i;
                    float l = accv[i] + s_bo[lr];
                    if (l > m) { s = s * __expf(m - l) + 1.f; m = l; a = r0 + lr; }
                    else       { s += __expf(l - m); }
                }
            }
            s_wm[warp] = m; s_wa[warp] = a; s_ws[warp] = s;
        }
        __syncthreads();

        // warp0: block partial merge + publish self-tagged slot
        if (warp == 0) {
            float mo = (lane < NWARP) ? s_wm[lane] : -INFINITY;
            float so = (lane < NWARP) ? s_ws[lane] : 0.f;
            int   ao = (lane < NWARP) ? s_wa[lane] : 0x7fffffff;
            float m = mo; int a = ao;
#pragma unroll
            for (int off = 16; off; off >>= 1) {
                float m2 = __shfl_xor_sync(0xffffffffu, m, off);
                int   a2 = __shfl_xor_sync(0xffffffffu, a, off);
                if (m2 > m || (m2 == m && a2 < a)) { m = m2; a = a2; }
            }
            float sc = (lane < NWARP) ? so * __expf(mo - m) : 0.f;
#pragma unroll
            for (int off = 16; off; off >>= 1)
                sc += __shfl_xor_sync(0xffffffffu, sc, off);
            if (lane == 0)
                stvol_f4(&g_pslot[par][b].v,
                         make_float4(m, sc, __int_as_float(a), ttag));
        }

        // ===== result: block0 aggregates, others poll one line =====
        if (b == 0) {
            if (ps < NB) {
                float4 p;
                do { p = ldvol_f4(&g_pslot[par][ps].v); } while (p.w != ttag);
                s_pm[ps] = p.x; s_ps[ps] = p.y; s_pa[ps] = __float_as_int(p.z);
            }
            __syncthreads();
            if (warp == 0) {
                float mi[5], si[5]; int ai[5];
#pragma unroll
                for (int i = 0; i < 5; i++) {
                    int idx = lane + 32 * i;
                    bool vld = idx < NB;
                    mi[i] = vld ? s_pm[idx] : -INFINITY;
                    si[i] = vld ? s_ps[idx] : 0.f;
                    ai[i] = vld ? s_pa[idx] : 0x7fffffff;
                }
                float m = mi[0]; int a = ai[0];
#pragma unroll
                for (int i = 1; i < 5; i++)
                    if (mi[i] > m || (mi[i] == m && ai[i] < a)) { m = mi[i]; a = ai[i]; }
#pragma unroll
                for (int off = 16; off; off >>= 1) {
                    float m2 = __shfl_xor_sync(0xffffffffu, m, off);
                    int   a2 = __shfl_xor_sync(0xffffffffu, a, off);
                    if (m2 > m || (m2 == m && a2 < a)) { m = m2; a = a2; }
                }
                float sc = 0.f;
#pragma unroll
                for (int i = 0; i < 5; i++) sc += si[i] * __expf(mi[i] - m);
#pragma unroll
                for (int off = 16; off; off >>= 1)
                    sc += __shfl_xor_sync(0xffffffffu, sc, off);
                if (lane == 0) {
                    float lp = -__logf(sc);
                    s_bc[0] = __int_as_float(a);
                    s_bc[1] = lp;
                    stvol_f4(&g_rp.v, make_float4(__int_as_float(a), lp, ttag, 0.f));
                }
            }
            __syncthreads();
        } else {
            if (tid == 0) {
                float4 p;
                do { p = ldvol_f4(&g_rp.v); } while (p.z != ttag);
                s_bc[0] = p.x; s_bc[1] = p.y;
            }
            __syncthreads();
        }

        const int   pred    = __float_as_int(s_bc[0]);
        const float logp    = s_bc[1];
        const bool  emitted = (pred != 0);

        if (b == 0 && tid == 0) {
            if (t < out_size) out[t] = emitted ? (float)pred : 0.0f;
            if (emitted) score += logp;
        }

        // ===== emission: LSTM + y/dv broadcasts =====
        if (emitted) {
            e += 1.0f;

            s_z[tid] = __ldg(&embed[(size_t)pred * DUNITS + tid]);  // ey
            __syncthreads();

            for (int lr = warp; lr < 4 * nk; lr += NWARP) {
                const float4* r4 = (const float4*)(sWih + lr * DUNITS);
                const float4* e4 = (const float4*)s_z;
                float acc = 0.f;
#pragma unroll
                for (int q = 0; q < 4; q++) {
                    float4 w = r4[lane + 32 * q], ev = e4[lane + 32 * q];
                    acc += w.x * ev.x + w.y * ev.y + w.z * ev.z + w.w * ev.w;
                }
                for (int off = 16; off; off >>= 1)
                    acc += __shfl_down_sync(0xffffffffu, acc, off);
                if (lane == 0) s_gt[lr] = s_bs[lr] + s_gh[lr] + acc;
            }
            __syncthreads();

            if (warp == 0) {
                float yv = 0.f;
                if (lane < nk) {
                    float gi_ = s_gt[4 * lane + 0], gf_ = s_gt[4 * lane + 1];
                    float gg_ = s_gt[4 * lane + 2], go_ = s_gt[4 * lane + 3];
                    float c  = s_c[lane];
                    float cn = sigm(gf_) * c + sigm(gi_) * tanhf(gg_);
                    yv = sigm(go_) * tanhf(cn);
                    s_c[lane] = cn;
                }
                float y0 = __shfl_sync(0xffffffffu, yv, 0);
                float y1 = __shfl_sync(0xffffffffu, yv, 1);
                float y2 = __shfl_sync(0xffffffffu, yv, 2);
                float y3 = __shfl_sync(0xffffffffu, yv, 3);
                if (lane == 0) {
                    stvol_f4(&g_yslot[b].pay, make_float4(y0, y1, y2, y3));
                    st_release_f32(&g_yslot[b].tag, e);
                }
            }
            if (b == 0) {
                if (ps < NB) {
                    while (ld_acquire_f32(&g_yslot[ps].tag) != e) {}
                    float4 p = ldvol_f4(&g_yslot[ps].pay);
                    s_y[pk0] = p.x;
                    if (pnk > 1) s_y[pk0 + 1] = p.y;
                    if (pnk > 2) s_y[pk0 + 2] = p.z;
                    if (pnk > 3) s_y[pk0 + 3] = p.w;
                }
                __syncthreads();
                if (tid < DUNITS / 4) stvol_f4(&g_ybc[tid], ((const float4*)s_y)[tid]);
                __syncthreads();
                if (tid == 0) st_release_f32(&g_ry, e);
            } else {
                if (tid == 0) { while (ld_acquire_f32(&g_ry) != e) {} }
                __syncthreads();
                if (tid < DUNITS / 4) ((float4*)s_y)[tid] = __ldcv(&g_ybc[tid]);
                __syncthreads();
            }

            // dv chunk (warp0 everywhere)
            if (warp == 0) {
                float dvp[4] = {0.f, 0.f, 0.f, 0.f};
#pragma unroll 4
                for (int r = 0; r < 4; r++) {
                    if (r < nk) {
                        const float4* r4 = (const float4*)(sWdec + r * DUNITS);
                        const float4* y4 = (const float4*)s_y;
                        float a = 0.f;
#pragma unroll
                        for (int q = 0; q < 4; q++) {
                            float4 w = r4[lane + 32 * q], yv = y4[lane + 32 * q];
                            a += w.x * yv.x + w.y * yv.y + w.z * yv.z + w.w * yv.w;
                        }
                        for (int off = 16; off; off >>= 1)
                            a += __shfl_down_sync(0xffffffffu, a, off);
                        dvp[r] = a;
                    }
                }
                if (lane == 0) {
                    stvol_f4(&g_dvslot[b].pay,
                             make_float4(dvp[0], dvp[1], dvp[2], dvp[3]));
                    st_release_f32(&g_dvslot[b].tag, e);
                }
            }
            if (b == 0) {
                if (warp >= 5) {
                    for (int g = warp - 5; g < 4 * nk; g += (NWARP - 5)) {
                        const float4* r4 = (const float4*)(sWhh + g * DUNITS);
                        const float4* y4 = (const float4*)s_y;
                        float a = 0.f;
#pragma unroll
                        for (int q = 0; q < 4; q++) {
                            float4 w = r4[lane + 32 * q], yv = y4[lane + 32 * q];
                            a += w.x * yv.x + w.y * yv.y + w.z * yv.z + w.w * yv.w;
                        }
                        for (int off = 16; off; off >>= 1)
                            a += __shfl_down_sync(0xffffffffu, a, off);
                        if (lane == 0) s_gh[g] = a;
                    }
                } else if (ps < NB) {
                    while (ld_acquire_f32(&g_dvslot[ps].tag) != e) {}
                    float4 p = ldvol_f4(&g_dvslot[ps].pay);
                    s_dv[pk0] = p.x;
                    if (pnk > 1) s_dv[pk0 + 1] = p.y;
                    if (pnk > 2) s_dv[pk0 + 2] = p.z;
                    if (pnk > 3) s_dv[pk0 + 3] = p.w;
                }
                __syncthreads();
                if (tid < JOINT / 4) stvol_f4(&g_dvbc[tid], ((const float4*)s_dv)[tid]);
                __syncthreads();
                if (tid == 0) st_release_f32(&g_rdv, e);
            } else {
                if (warp >= 1) {
                    for (int g = warp - 1; g < 4 * nk; g += (NWARP - 1)) {
                        const float4* r4 = (const float4*)(sWhh + g * DUNITS);
                        const float4* y4 = (const float4*)s_y;
                        float a = 0.f;
#pragma unroll
                        for (int q = 0; q < 4; q++) {
                            float4 w = r4[lane + 32 * q], yv = y4[lane + 32 * q];
                            a += w.x * yv.x + w.y * yv.y + w.z * yv.z + w.w * yv.w;
                        }
                        for (int off = 16; off; off >>= 1)
                            a += __shfl_down_sync(0xffffffffu, a, off);
                        if (lane == 0) s_gh[g] = a;
                    }
                }
                if (tid == 0) { while (ld_acquire_f32(&g_rdv) != e) {} }
                __syncthreads();
                if (tid < JOINT / 4) ((float4*)s_dv)[tid] = __ldcv(&g_dvbc[tid]);
                __syncthreads();
            }
        }
    }

    if (b == 0) {
        if (tid == 0 && out_size > T_FRAMES) out[T_FRAMES] = score;
        for (int i = T_FRAMES + 1 + tid; i < out_size; i += NT) out[i] = 0.f;
    }
}

// ---------------- launch ----------------
extern "C" void kernel_launch(void* const* d_in, const int* in_sizes, int n_in,
                              void* d_out, int out_size) {
    (void)in_sizes; (void)n_in;
    const float* h     = (const float*)d_in[0];
    const float* embed = (const float*)d_in[1];
    const float* Wih   = (const float*)d_in[2];
    const float* Whh   = (const float*)d_in[3];
    const float* bih   = (const float*)d_in[4];
    const float* bhh   = (const float*)d_in[5];
    const float* Wenc  = (const float*)d_in[6];
    const float* benc  = (const float*)d_in[7];
    const float* Wdec  = (const float*)d_in[8];
    const float* Wout  = (const float*)d_in[9];
    const float* bout  = (const float*)d_in[10];
    float* out = (float*)d_out;

    const int smem_bytes = SM_TOTAL_FLOATS * (int)sizeof(float);
    cudaFuncSetAttribute(decode_kernel,
                         cudaFuncAttributeMaxDynamicSharedMemorySize, smem_bytes);

    hp_kernel<<<T_FRAMES / 8, 256>>>(h, Wenc, benc);
    decode_kernel<<<NB, NT, smem_bytes>>>(embed, Wih, Whh, bih, bhh,
                                          Wdec, Wout, bout, out, out_size);
}

// round 10
// speedup vs baseline: 1.2513x; 1.2513x over previous
#include <cuda_runtime.h>
#include <math.h>
#include <stdint.h>

#define T_FRAMES 2048
#define EPROJS   1024
#define DUNITS   512
#define JOINT    512
#define ODIM     10000
#define NB       148
#define NT       512
#define NWARP    (NT / 32)

// ---------------- global scratch ----------------
__device__ float  g_hp[T_FRAMES * JOINT];   // encoder-side joint projection
__device__ float  g_yv[DUNITS];             // prediction-net state (per emission epoch)
__device__ float  g_dv[JOINT];              // dv = Wdec*y (per emission epoch)
__device__ float4 g_part[2][NB];            // (max, sumexp, argmax-bits, unused) contiguous
__device__ __align__(128) unsigned g_cp;    // partial arrivals: NB per step
__device__ __align__(128) unsigned g_cy;    // y arrivals: NB per emission epoch
__device__ __align__(128) unsigned g_cdv;   // dv arrivals: NB per emission epoch

__device__ __forceinline__ void red_release(unsigned* p) {
    asm volatile("red.release.gpu.global.add.u32 [%0], 1;" :: "l"(p) : "memory");
}
__device__ __forceinline__ unsigned ld_acquire(unsigned* p) {
    unsigned v;
    asm volatile("ld.acquire.gpu.global.u32 %0, [%1];" : "=r"(v) : "l"(p) : "memory");
    return v;
}
__device__ __forceinline__ float sigm(float x) { return 1.f / (1.f + expf(-x)); }

// 4 staggered pollers: lane 0 of warps 0..3
#define MULTI_POLL(ctr, tgt)                                              \
    do {                                                                  \
        if (tid < 128 && (tid & 31) == 0) {                               \
            while (ld_acquire(&(ctr)) < (tgt)) {}                         \
        }                                                                 \
        __syncthreads();                                                  \
    } while (0)

// ---------------- hp = h @ W_enc^T + b_enc ----------------
__global__ void hp_kernel(const float* __restrict__ h,
                          const float* __restrict__ Wenc,
                          const float* __restrict__ benc) {
    if (blockIdx.x == 0 && threadIdx.x == 0) { g_cp = 0u; g_cy = 0u; g_cdv = 0u; }

    __shared__ float sh[8 * EPROJS];
    const int tid  = threadIdx.x;
    const int warp = tid >> 5;
    const int lane = tid & 31;
    const size_t t0 = (size_t)blockIdx.x * 8;

    const float4* hsrc = (const float4*)(h + t0 * EPROJS);
    float4* sh4 = (float4*)sh;
    for (int i = tid; i < 8 * EPROJS / 4; i += 256) sh4[i] = hsrc[i];
    __syncthreads();

    const float4* w0 = (const float4*)Wenc;
    for (int pass = 0; pass < 16; pass++) {
        int jb = (pass * 8 + warp) * 4;
        float acc[8][4];
#pragma unroll
        for (int tt = 0; tt < 8; tt++)
#pragma unroll
            for (int jj = 0; jj < 4; jj++) acc[tt][jj] = 0.f;

        for (int qq = 0; qq < 8; qq++) {
            int q = qq * 32 + lane;
            float4 w[4];
#pragma unroll
            for (int jj = 0; jj < 4; jj++)
                w[jj] = w0[(size_t)(jb + jj) * (EPROJS / 4) + q];
#pragma unroll
            for (int tt = 0; tt < 8; tt++) {
                float4 hv = sh4[tt * (EPROJS / 4) + q];
#pragma unroll
                for (int jj = 0; jj < 4; jj++)
                    acc[tt][jj] += hv.x * w[jj].x + hv.y * w[jj].y +
                                   hv.z * w[jj].z + hv.w * w[jj].w;
            }
        }
#pragma unroll
        for (int tt = 0; tt < 8; tt++) {
#pragma unroll
            for (int jj = 0; jj < 4; jj++) {
                float v = acc[tt][jj];
                for (int off = 16; off; off >>= 1)
                    v += __shfl_down_sync(0xffffffffu, v, off);
                if (lane == 0)
                    g_hp[(t0 + tt) * JOINT + jb + jj] = v + benc[jb + jj];
            }
        }
    }
}

// ---------------- smem layout (floats) ----------------
#define SM_WOUT   0
#define SM_WHH    (SM_WOUT + 68 * JOINT)
#define SM_WIH    (SM_WHH + 16 * DUNITS)
#define SM_WDEC   (SM_WIH + 16 * DUNITS)
#define SM_Y      (SM_WDEC + 4 * DUNITS)
#define SM_DV     (SM_Y + DUNITS)
#define SM_Z      (SM_DV + JOINT)          /* reused as ey during LSTM */
#define SM_HP     (SM_Z + JOINT)
#define SM_BO     (SM_HP + JOINT)
#define SM_BS     (SM_BO + 68)
#define SM_GH     (SM_BS + 16)
#define SM_GT     (SM_GH + 16)
#define SM_C      (SM_GT + 16)
#define SM_BC     (SM_C + 4)
#define SM_WM     (SM_BC + 4)
#define SM_WA     (SM_WM + NWARP)
#define SM_WS     (SM_WA + NWARP)
#define SM_TOTAL_FLOATS (SM_WS + NWARP)

__global__ void __launch_bounds__(NT, 1)
decode_kernel(const float* __restrict__ embed,
              const float* __restrict__ Wih, const float* __restrict__ Whh,
              const float* __restrict__ bih, const float* __restrict__ bhh,
              const float* __restrict__ Wdec, const float* __restrict__ Wout,
              const float* __restrict__ bout,
              float* __restrict__ out, int out_size) {
    extern __shared__ float sm[];
    const int b    = blockIdx.x;
    const int tid  = threadIdx.x;
    const int warp = tid >> 5;
    const int lane = tid & 31;

    const int r0 = (b * ODIM) / NB, r1 = ((b + 1) * ODIM) / NB, nr = r1 - r0;
    const int k0 = (b * DUNITS) / NB, k1 = ((b + 1) * DUNITS) / NB, nk = k1 - k0;

    float* sWout = sm + SM_WOUT;
    float* sWhh  = sm + SM_WHH;
    float* sWih  = sm + SM_WIH;
    float* sWdec = sm + SM_WDEC;
    float* s_y   = sm + SM_Y;
    float* s_dv  = sm + SM_DV;
    float* s_z   = sm + SM_Z;
    float* s_hp  = sm + SM_HP;
    float* s_bo  = sm + SM_BO;
    float* s_bs  = sm + SM_BS;
    float* s_gh  = sm + SM_GH;
    float* s_gt  = sm + SM_GT;
    float* s_c   = sm + SM_C;
    float* s_bc  = sm + SM_BC;
    float* s_wm  = sm + SM_WM;
    int*   s_wa  = (int*)(sm + SM_WA);
    float* s_ws  = sm + SM_WS;

    // ---- load weights into shared (resident for entire decode) ----
    {
        const float4* src = (const float4*)(Wout + (size_t)r0 * JOINT);
        float4* dst = (float4*)sWout;
        for (int i = tid; i < nr * (JOINT / 4); i += NT) dst[i] = src[i];
    }
    for (int i = tid; i < nr; i += NT) s_bo[i] = bout[r0 + i];
    {
        const int ng = 4 * nk;
        for (int i = tid; i < ng * (DUNITS / 4); i += NT) {
            int lr = i / (DUNITS / 4), x = i % (DUNITS / 4);
            int gi = lr & 3, ki = lr >> 2;
            size_t G = (size_t)(gi * DUNITS + k0 + ki);
            ((float4*)sWhh)[i] = ((const float4*)(Whh + G * DUNITS))[x];
            ((float4*)sWih)[i] = ((const float4*)(Wih + G * DUNITS))[x];
        }
        for (int i = tid; i < ng; i += NT) {
            int gi = i & 3, ki = i >> 2;
            int G = gi * DUNITS + k0 + ki;
            s_bs[i] = bih[G] + bhh[G];
        }
    }
    {
        // zero then load Wdec rows (rows >= nk stay zero; read in interleaved dv)
        for (int i = tid; i < 4 * (DUNITS / 4); i += NT)
            ((float4*)sWdec)[i] = make_float4(0.f, 0.f, 0.f, 0.f);
        __syncthreads();
        const float4* src = (const float4*)(Wdec + (size_t)k0 * DUNITS);
        float4* dst = (float4*)sWdec;
        for (int i = tid; i < nk * (DUNITS / 4); i += NT) dst[i] = src[i];
    }
    __syncthreads();

    unsigned e = 1;   // emission epoch (prologue = 1)

    // ---- prologue: y0 from zero input / zero state ----
    if (warp == 0) {
        if (lane < nk) {
            float gi_ = s_bs[4 * lane + 0];
            float gg_ = s_bs[4 * lane + 2];
            float go_ = s_bs[4 * lane + 3];
            float c  = sigm(gi_) * tanhf(gg_);
            float yv = sigm(go_) * tanhf(c);
            s_c[lane] = c;
            g_yv[k0 + lane] = yv;
        }
        __syncwarp();
        if (lane == 0) red_release(&g_cy);
    }
    MULTI_POLL(g_cy, NB * e);
    s_y[tid] = __ldcv(&g_yv[tid]);
    __syncthreads();

    // dv rows interleaved in warp0; gh rows on warps 1..15
    if (warp == 0) {
        const float4* y4 = (const float4*)s_y;
        float acc0 = 0.f, acc1 = 0.f, acc2 = 0.f, acc3 = 0.f;
#pragma unroll
        for (int q = 0; q < 4; q++) {
            float4 yv = y4[lane + 32 * q];
            float4 w0 = ((const float4*)(sWdec + 0 * DUNITS))[lane + 32 * q];
            float4 w1 = ((const float4*)(sWdec + 1 * DUNITS))[lane + 32 * q];
            float4 w2 = ((const float4*)(sWdec + 2 * DUNITS))[lane + 32 * q];
            float4 w3 = ((const float4*)(sWdec + 3 * DUNITS))[lane + 32 * q];
            acc0 += w0.x * yv.x + w0.y * yv.y + w0.z * yv.z + w0.w * yv.w;
            acc1 += w1.x * yv.x + w1.y * yv.y + w1.z * yv.z + w1.w * yv.w;
            acc2 += w2.x * yv.x + w2.y * yv.y + w2.z * yv.z + w2.w * yv.w;
            acc3 += w3.x * yv.x + w3.y * yv.y + w3.z * yv.z + w3.w * yv.w;
        }
#pragma unroll
        for (int off = 16; off; off >>= 1) {
            acc0 += __shfl_down_sync(0xffffffffu, acc0, off);
            acc1 += __shfl_down_sync(0xffffffffu, acc1, off);
            acc2 += __shfl_down_sync(0xffffffffu, acc2, off);
            acc3 += __shfl_down_sync(0xffffffffu, acc3, off);
        }
        if (lane == 0) {
            g_dv[k0 + 0] = acc0;
            if (nk > 1) g_dv[k0 + 1] = acc1;
            if (nk > 2) g_dv[k0 + 2] = acc2;
            if (nk > 3) g_dv[k0 + 3] = acc3;
            red_release(&g_cdv);
        }
    } else {
        for (int g = warp - 1; g < 4 * nk; g += (NWARP - 1)) {
            const float4* r4 = (const float4*)(sWhh + g * DUNITS);
            const float4* y4 = (const float4*)s_y;
            float a = 0.f;
#pragma unroll
            for (int q = 0; q < 4; q++) {
                float4 w = r4[lane + 32 * q], yv = y4[lane + 32 * q];
                a += w.x * yv.x + w.y * yv.y + w.z * yv.z + w.w * yv.w;
            }
            for (int off = 16; off; off >>= 1)
                a += __shfl_down_sync(0xffffffffu, a, off);
            if (lane == 0) s_gh[g] = a;
        }
    }
    MULTI_POLL(g_cdv, NB * e);
    s_dv[tid] = __ldcv(&g_dv[tid]);   // own-tid, no bar needed before z
    s_hp[tid] = g_hp[tid];            // hp row 0

    float score = 0.f;

    for (int t = 0; t < T_FRAMES; t++) {
        const int par = t & 1;

        // ===== z fully local: z = tanh(hp_t + dv) =====
        s_z[tid] = tanhf(s_hp[tid] + s_dv[tid]);
        __syncthreads();

        float4 zr[4];
#pragma unroll
        for (int q = 0; q < 4; q++) zr[q] = ((const float4*)s_z)[lane + 32 * q];

        // prefetch next hp row
        float hpn = (t + 1 < T_FRAMES)
                        ? __ldg(&g_hp[(size_t)(t + 1) * JOINT + tid]) : 0.f;

        // ===== logits rows =====
        float accv[5];
        int rcount = 0;
        for (int lr = warp, i = 0; lr < nr; lr += NWARP, i++) {
            const float4* r4 = (const float4*)(sWout + lr * JOINT);
            float a = 0.f;
#pragma unroll
            for (int q = 0; q < 4; q++) {
                float4 w = r4[lane + 32 * q];
                a += w.x * zr[q].x + w.y * zr[q].y + w.z * zr[q].z + w.w * zr[q].w;
            }
            accv[i] = a;
            rcount = i + 1;
        }
        s_hp[tid] = hpn;
#pragma unroll
        for (int i = 0; i < 5; i++) {
            float a = (i < rcount) ? accv[i] : 0.f;
            a += __shfl_down_sync(0xffffffffu, a, 16);
            a += __shfl_down_sync(0xffffffffu, a, 8);
            a += __shfl_down_sync(0xffffffffu, a, 4);
            a += __shfl_down_sync(0xffffffffu, a, 2);
            a += __shfl_down_sync(0xffffffffu, a, 1);
            accv[i] = a;
        }

        // per-warp online softmax stats
        if (lane == 0) {
            float m = -INFINITY, s = 0.f;
            int a = 0x7fffffff;
#pragma unroll
            for (int i = 0; i < 5; i++) {
                if (i < rcount) {
                    int lr = warp + NWARP * i;
                    float l = accv[i] + s_bo[lr];
                    if (l > m) { s = s * __expf(m - l) + 1.f; m = l; a = r0 + lr; }
                    else       { s += __expf(l - m); }
                }
            }
            s_wm[warp] = m; s_wa[warp] = a; s_ws[warp] = s;
        }
        __syncthreads();

        // warp0: block merge + publish partial + release
        if (warp == 0) {
            float mo = (lane < NWARP) ? s_wm[lane] : -INFINITY;
            float so = (lane < NWARP) ? s_ws[lane] : 0.f;
            int   ao = (lane < NWARP) ? s_wa[lane] : 0x7fffffff;
            float m = mo; int a = ao;
#pragma unroll
            for (int off = 16; off; off >>= 1) {
                float m2 = __shfl_xor_sync(0xffffffffu, m, off);
                int   a2 = __shfl_xor_sync(0xffffffffu, a, off);
                if (m2 > m || (m2 == m && a2 < a)) { m = m2; a = a2; }
            }
            float sc = (lane < NWARP) ? so * __expf(mo - m) : 0.f;
#pragma unroll
            for (int off = 16; off; off >>= 1)
                sc += __shfl_xor_sync(0xffffffffu, sc, off);
            if (lane == 0) {
                g_part[par][b] = make_float4(m, sc, __int_as_float(a), 0.f);
                red_release(&g_cp);
            }
        }

        // ===== wait partials (4 pollers) =====
        MULTI_POLL(g_cp, (unsigned)NB * (unsigned)(t + 1));

        // ===== parallel global merge: warps 0..4 read+merge 32 slots each ====
        if (warp < 5) {
            int idx = warp * 32 + lane;
            bool vld = idx < NB;
            float m, s; int a;
            if (vld) {
                float4 p = __ldcv(&g_part[par][idx]);
                m = p.x; s = p.y; a = __float_as_int(p.z);
            } else { m = -INFINITY; s = 0.f; a = 0x7fffffff; }
#pragma unroll
            for (int off = 16; off; off >>= 1) {
                float m2 = __shfl_xor_sync(0xffffffffu, m, off);
                float s2 = __shfl_xor_sync(0xffffffffu, s, off);
                int   a2 = __shfl_xor_sync(0xffffffffu, a, off);
                float M  = (m2 > m) ? m2 : m;
                int   A  = (m2 > m || (m2 == m && a2 < a)) ? a2 : a;
                float e1 = (m  == -INFINITY) ? 0.f : __expf(m  - M);
                float e2 = (m2 == -INFINITY) ? 0.f : __expf(m2 - M);
                s = s * e1 + s2 * e2;
                m = M; a = A;
            }
            if (lane == 0) { s_wm[warp] = m; s_wa[warp] = a; s_ws[warp] = s; }
        }
        __syncthreads();
        if (warp == 0) {
            float m = (lane < 5) ? s_wm[lane] : -INFINITY;
            float s = (lane < 5) ? s_ws[lane] : 0.f;
            int   a = (lane < 5) ? s_wa[lane] : 0x7fffffff;
#pragma unroll
            for (int off = 4; off; off >>= 1) {
                float m2 = __shfl_xor_sync(0xffffffffu, m, off);
                float s2 = __shfl_xor_sync(0xffffffffu, s, off);
                int   a2 = __shfl_xor_sync(0xffffffffu, a, off);
                float M  = (m2 > m) ? m2 : m;
                int   A  = (m2 > m || (m2 == m && a2 < a)) ? a2 : a;
                float e1 = (m  == -INFINITY) ? 0.f : __expf(m  - M);
                float e2 = (m2 == -INFINITY) ? 0.f : __expf(m2 - M);
                s = s * e1 + s2 * e2;
                m = M; a = A;
            }
            if (lane == 0) {
                s_bc[0] = __int_as_float(a);
                s_bc[1] = -__logf(s);
            }
        }
        __syncthreads();

        const int   pred    = __float_as_int(s_bc[0]);
        const float logp    = s_bc[1];
        const bool  emitted = (pred != 0);

        if (b == 0 && tid == 0) {
            if (t < out_size) out[t] = emitted ? (float)pred : 0.0f;
            if (emitted) score += logp;
        }

        // ===== emission: LSTM + y handoff + dv/gh refresh =====
        if (emitted) {
            e++;
            s_z[tid] = __ldg(&embed[(size_t)pred * DUNITS + tid]);  // ey
            __syncthreads();

            for (int lr = warp; lr < 4 * nk; lr += NWARP) {
                const float4* r4 = (const float4*)(sWih + lr * DUNITS);
                const float4* e4 = (const float4*)s_z;
                float acc = 0.f;
#pragma unroll
                for (int q = 0; q < 4; q++) {
                    float4 w = r4[lane + 32 * q], ev = e4[lane + 32 * q];
                    acc += w.x * ev.x + w.y * ev.y + w.z * ev.z + w.w * ev.w;
                }
                for (int off = 16; off; off >>= 1)
                    acc += __shfl_down_sync(0xffffffffu, acc, off);
                if (lane == 0) s_gt[lr] = s_bs[lr] + s_gh[lr] + acc;
            }
            __syncthreads();

            if (warp == 0) {
                if (lane < nk) {
                    float gi_ = s_gt[4 * lane + 0], gf_ = s_gt[4 * lane + 1];
                    float gg_ = s_gt[4 * lane + 2], go_ = s_gt[4 * lane + 3];
                    float c  = s_c[lane];
                    float cn = sigm(gf_) * c + sigm(gi_) * tanhf(gg_);
                    float yn = sigm(go_) * tanhf(cn);
                    s_c[lane] = cn;
                    g_yv[k0 + lane] = yn;
                }
                __syncwarp();
                if (lane == 0) red_release(&g_cy);
            }
            MULTI_POLL(g_cy, NB * e);
            s_y[tid] = __ldcv(&g_yv[tid]);
            __syncthreads();

            // dv interleaved (warp0) + gh refresh (warps 1..15)
            if (warp == 0) {
                const float4* y4 = (const float4*)s_y;
                float acc0 = 0.f, acc1 = 0.f, acc2 = 0.f, acc3 = 0.f;
#pragma unroll
                for (int q = 0; q < 4; q++) {
                    float4 yv = y4[lane + 32 * q];
                    float4 w0 = ((const float4*)(sWdec + 0 * DUNITS))[lane + 32 * q];
                    float4 w1 = ((const float4*)(sWdec + 1 * DUNITS))[lane + 32 * q];
                    float4 w2 = ((const float4*)(sWdec + 2 * DUNITS))[lane + 32 * q];
                    float4 w3 = ((const float4*)(sWdec + 3 * DUNITS))[lane + 32 * q];
                    acc0 += w0.x * yv.x + w0.y * yv.y + w0.z * yv.z + w0.w * yv.w;
                    acc1 += w1.x * yv.x + w1.y * yv.y + w1.z * yv.z + w1.w * yv.w;
                    acc2 += w2.x * yv.x + w2.y * yv.y + w2.z * yv.z + w2.w * yv.w;
                    acc3 += w3.x * yv.x + w3.y * yv.y + w3.z * yv.z + w3.w * yv.w;
                }
#pragma unroll
                for (int off = 16; off; off >>= 1) {
                    acc0 += __shfl_down_sync(0xffffffffu, acc0, off);
                    acc1 += __shfl_down_sync(0xffffffffu, acc1, off);
                    acc2 += __shfl_down_sync(0xffffffffu, acc2, off);
                    acc3 += __shfl_down_sync(0xffffffffu, acc3, off);
                }
                if (lane == 0) {
                    g_dv[k0 + 0] = acc0;
                    if (nk > 1) g_dv[k0 + 1] = acc1;
                    if (nk > 2) g_dv[k0 + 2] = acc2;
                    if (nk > 3) g_dv[k0 + 3] = acc3;
                    red_release(&g_cdv);
                }
            } else {
                for (int g = warp - 1; g < 4 * nk; g += (NWARP - 1)) {
                    const float4* r4 = (const float4*)(sWhh + g * DUNITS);
                    const float4* y4 = (const float4*)s_y;
                    float a = 0.f;
#pragma unroll
                    for (int q = 0; q < 4; q++) {
                        float4 w = r4[lane + 32 * q], yv = y4[lane + 32 * q];
                        a += w.x * yv.x + w.y * yv.y + w.z * yv.z + w.w * yv.w;
                    }
                    for (int off = 16; off; off >>= 1)
                        a += __shfl_down_sync(0xffffffffu, a, off);
                    if (lane == 0) s_gh[g] = a;
                }
            }
            MULTI_POLL(g_cdv, NB * e);
            s_dv[tid] = __ldcv(&g_dv[tid]);   // own-tid; next use is loop-top z
        }
    }

    if (b == 0) {
        if (tid == 0 && out_size > T_FRAMES) out[T_FRAMES] = score;
        for (int i = T_FRAMES + 1 + tid; i < out_size; i += NT) out[i] = 0.f;
    }
}

// ---------------- launch ----------------
extern "C" void kernel_launch(void* const* d_in, const int* in_sizes, int n_in,
                              void* d_out, int out_size) {
    (void)in_sizes; (void)n_in;
    const float* h     = (const float*)d_in[0];
    const float* embed = (const float*)d_in[1];
    const float* Wih   = (const float*)d_in[2];
    const float* Whh   = (const float*)d_in[3];
    const float* bih   = (const float*)d_in[4];
    const float* bhh   = (const float*)d_in[5];
    const float* Wenc  = (const float*)d_in[6];
    const float* benc  = (const float*)d_in[7];
    const float* Wdec  = (const float*)d_in[8];
    const float* Wout  = (const float*)d_in[9];
    const float* bout  = (const float*)d_in[10];
    float* out = (float*)d_out;

    const int smem_bytes = SM_TOTAL_FLOATS * (int)sizeof(float);
    cudaFuncSetAttribute(decode_kernel,
                         cudaFuncAttributeMaxDynamicSharedMemorySize, smem_bytes);

    hp_kernel<<<T_FRAMES / 8, 256>>>(h, Wenc, benc);
    decode_kernel<<<NB, NT, smem_bytes>>>(embed, Wih, Whh, bih, bhh,
                                          Wdec, Wout, bout, out, out_size);
}

// round 14
// speedup vs baseline: 1.4694x; 1.1743x over previous
#include <cuda_runtime.h>
#include <math.h>
#include <stdint.h>

#define T_FRAMES 2048
#define EPROJS   1024
#define DUNITS   512
#define JOINT    512
#define ODIM     10000
#define NB       148
#define NT       256
#define NWARP    (NT / 32)
#define RROWS    9            // Wout rows per warp held in registers (9*8=72 >= 68)

// ---------------- global scratch ----------------
__device__ float  g_hp[T_FRAMES * JOINT];   // encoder-side joint projection
__device__ float  g_yv[DUNITS];             // prediction-net state (per emission epoch)
__device__ float  g_dv[JOINT];              // dv = Wdec*y (per emission epoch)
__device__ float4 g_part[2][NB];            // (max, sumexp, argmax-bits, unused)
__device__ __align__(128) unsigned g_cp;    // partial arrivals: NB per step
__device__ __align__(128) unsigned g_cy;    // y arrivals: NB per emission epoch
__device__ __align__(128) unsigned g_cdv;   // dv arrivals: NB per emission epoch

__device__ __forceinline__ void red_release(unsigned* p) {
    asm volatile("red.release.gpu.global.add.u32 [%0], 1;" :: "l"(p) : "memory");
}
__device__ __forceinline__ unsigned ld_acquire(unsigned* p) {
    unsigned v;
    asm volatile("ld.acquire.gpu.global.u32 %0, [%1];" : "=r"(v) : "l"(p) : "memory");
    return v;
}
__device__ __forceinline__ float sigm(float x) { return 1.f / (1.f + expf(-x)); }

// single poller (R6-proven): lane0 of warp0 only
#define ONE_POLL(ctr, tgt)                                                \
    do {                                                                  \
        if (tid == 0) { while (ld_acquire(&(ctr)) < (tgt)) {} }           \
        __syncthreads();                                                  \
    } while (0)

// ---------------- hp = h @ W_enc^T + b_enc ----------------
__global__ void hp_kernel(const float* __restrict__ h,
                          const float* __restrict__ Wenc,
                          const float* __restrict__ benc) {
    if (blockIdx.x == 0 && threadIdx.x == 0) { g_cp = 0u; g_cy = 0u; g_cdv = 0u; }

    __shared__ float sh[8 * EPROJS];
    const int tid  = threadIdx.x;
    const int warp = tid >> 5;
    const int lane = tid & 31;
    const size_t t0 = (size_t)blockIdx.x * 8;

    const float4* hsrc = (const float4*)(h + t0 * EPROJS);
    float4* sh4 = (float4*)sh;
    for (int i = tid; i < 8 * EPROJS / 4; i += 256) sh4[i] = hsrc[i];
    __syncthreads();

    const float4* w0 = (const float4*)Wenc;
    for (int pass = 0; pass < 16; pass++) {
        int jb = (pass * 8 + warp) * 4;
        float acc[8][4];
#pragma unroll
        for (int tt = 0; tt < 8; tt++)
#pragma unroll
            for (int jj = 0; jj < 4; jj++) acc[tt][jj] = 0.f;

        for (int qq = 0; qq < 8; qq++) {
            int q = qq * 32 + lane;
            float4 w[4];
#pragma unroll
            for (int jj = 0; jj < 4; jj++)
                w[jj] = w0[(size_t)(jb + jj) * (EPROJS / 4) + q];
#pragma unroll
            for (int tt = 0; tt < 8; tt++) {
                float4 hv = sh4[tt * (EPROJS / 4) + q];
#pragma unroll
                for (int jj = 0; jj < 4; jj++)
                    acc[tt][jj] += hv.x * w[jj].x + hv.y * w[jj].y +
                                   hv.z * w[jj].z + hv.w * w[jj].w;
            }
        }
#pragma unroll
        for (int tt = 0; tt < 8; tt++) {
#pragma unroll
            for (int jj = 0; jj < 4; jj++) {
                float v = acc[tt][jj];
                for (int off = 16; off; off >>= 1)
                    v += __shfl_down_sync(0xffffffffu, v, off);
                if (lane == 0)
                    g_hp[(t0 + tt) * JOINT + jb + jj] = v + benc[jb + jj];
            }
        }
    }
}

// ---------------- smem layout (floats) ----------------
#define SM_WHH    0
#define SM_WIH    (SM_WHH + 16 * DUNITS)
#define SM_WDEC   (SM_WIH + 16 * DUNITS)
#define SM_Y      (SM_WDEC + 4 * DUNITS)
#define SM_DV     (SM_Y + DUNITS)
#define SM_Z      (SM_DV + JOINT)          /* reused as ey during LSTM */
#define SM_HP     (SM_Z + JOINT)
#define SM_BO     (SM_HP + JOINT)
#define SM_BS     (SM_BO + 72)
#define SM_GH     (SM_BS + 16)
#define SM_GT     (SM_GH + 16)
#define SM_C      (SM_GT + 16)
#define SM_BC     (SM_C + 4)
#define SM_WM     (SM_BC + 4)
#define SM_WA     (SM_WM + NWARP)
#define SM_WS     (SM_WA + NWARP)
#define SM_PM     (SM_WS + NWARP)
#define SM_PS     (SM_PM + NB)
#define SM_PA     (SM_PS + NB)
#define SM_TOTAL_FLOATS (SM_PA + NB)

__global__ void __launch_bounds__(NT, 1)
decode_kernel(const float* __restrict__ embed,
              const float* __restrict__ Wih, const float* __restrict__ Whh,
              const float* __restrict__ bih, const float* __restrict__ bhh,
              const float* __restrict__ Wdec, const float* __restrict__ Wout,
              const float* __restrict__ bout,
              float* __restrict__ out, int out_size) {
    extern __shared__ float sm[];
    const int b    = blockIdx.x;
    const int tid  = threadIdx.x;
    const int warp = tid >> 5;
    const int lane = tid & 31;

    const int r0 = (b * ODIM) / NB, r1 = ((b + 1) * ODIM) / NB, nr = r1 - r0;
    const int k0 = (b * DUNITS) / NB, k1 = ((b + 1) * DUNITS) / NB, nk = k1 - k0;

    float* sWhh  = sm + SM_WHH;
    float* sWih  = sm + SM_WIH;
    float* sWdec = sm + SM_WDEC;
    float* s_y   = sm + SM_Y;
    float* s_dv  = sm + SM_DV;
    float* s_z   = sm + SM_Z;
    float* s_hp  = sm + SM_HP;
    float* s_bo  = sm + SM_BO;
    float* s_bs  = sm + SM_BS;
    float* s_gh  = sm + SM_GH;
    float* s_gt  = sm + SM_GT;
    float* s_c   = sm + SM_C;
    float* s_bc  = sm + SM_BC;
    float* s_wm  = sm + SM_WM;
    int*   s_wa  = (int*)(sm + SM_WA);
    float* s_ws  = sm + SM_WS;
    float* s_pm  = sm + SM_PM;
    float* s_ps  = sm + SM_PS;
    int*   s_pa  = (int*)(sm + SM_PA);

    // ---- Wout slice into REGISTERS: row lr = warp + 8*i, cols lane + 32*j ----
    float wr[RROWS][16];
#pragma unroll
    for (int i = 0; i < RROWS; i++) {
        int lr = warp + NWARP * i;
        bool v = lr < nr;
        const float* wrow = Wout + (size_t)(r0 + (v ? lr : 0)) * JOINT;
#pragma unroll
        for (int j = 0; j < 16; j++)
            wr[i][j] = v ? __ldg(&wrow[lane + 32 * j]) : 0.f;
    }

    // ---- other weights into shared ----
    for (int i = tid; i < nr; i += NT) s_bo[i] = bout[r0 + i];
    {
        const int ng = 4 * nk;
        for (int i = tid; i < ng * (DUNITS / 4); i += NT) {
            int lr = i / (DUNITS / 4), x = i % (DUNITS / 4);
            int gi = lr & 3, ki = lr >> 2;
            size_t G = (size_t)(gi * DUNITS + k0 + ki);
            ((float4*)sWhh)[i] = ((const float4*)(Whh + G * DUNITS))[x];
            ((float4*)sWih)[i] = ((const float4*)(Wih + G * DUNITS))[x];
        }
        for (int i = tid; i < ng; i += NT) {
            int gi = i & 3, ki = i >> 2;
            int G = gi * DUNITS + k0 + ki;
            s_bs[i] = bih[G] + bhh[G];
        }
    }
    {
        for (int i = tid; i < 4 * (DUNITS / 4); i += NT)
            ((float4*)sWdec)[i] = make_float4(0.f, 0.f, 0.f, 0.f);
        __syncthreads();
        const float4* src = (const float4*)(Wdec + (size_t)k0 * DUNITS);
        float4* dst = (float4*)sWdec;
        for (int i = tid; i < nk * (DUNITS / 4); i += NT) dst[i] = src[i];
    }
    __syncthreads();

    unsigned e = 1;   // emission epoch (prologue = 1)

    // ---- prologue: y0 from zero input / zero state ----
    if (warp == 0) {
        if (lane < nk) {
            float gi_ = s_bs[4 * lane + 0];
            float gg_ = s_bs[4 * lane + 2];
            float go_ = s_bs[4 * lane + 3];
            float c  = sigm(gi_) * tanhf(gg_);
            float yv = sigm(go_) * tanhf(c);
            s_c[lane] = c;
            g_yv[k0 + lane] = yv;
        }
        __syncwarp();
        if (lane == 0) red_release(&g_cy);
    }
    ONE_POLL(g_cy, NB * e);
    if (tid < DUNITS / 4) ((float4*)s_y)[tid] = __ldcv(((const float4*)g_yv) + tid);
    __syncthreads();

    // dv (warp0, interleaved 4 rows) + gh (warps 1..7)
    if (warp == 0) {
        const float4* y4 = (const float4*)s_y;
        float a0 = 0.f, a1 = 0.f, a2 = 0.f, a3 = 0.f;
#pragma unroll
        for (int q = 0; q < 4; q++) {
            float4 yv = y4[lane + 32 * q];
            float4 w0 = ((const float4*)(sWdec + 0 * DUNITS))[lane + 32 * q];
            float4 w1 = ((const float4*)(sWdec + 1 * DUNITS))[lane + 32 * q];
            float4 w2 = ((const float4*)(sWdec + 2 * DUNITS))[lane + 32 * q];
            float4 w3 = ((const float4*)(sWdec + 3 * DUNITS))[lane + 32 * q];
            a0 += w0.x * yv.x + w0.y * yv.y + w0.z * yv.z + w0.w * yv.w;
            a1 += w1.x * yv.x + w1.y * yv.y + w1.z * yv.z + w1.w * yv.w;
            a2 += w2.x * yv.x + w2.y * yv.y + w2.z * yv.z + w2.w * yv.w;
            a3 += w3.x * yv.x + w3.y * yv.y + w3.z * yv.z + w3.w * yv.w;
        }
#pragma unroll
        for (int off = 16; off; off >>= 1) {
            a0 += __shfl_down_sync(0xffffffffu, a0, off);
            a1 += __shfl_down_sync(0xffffffffu, a1, off);
            a2 += __shfl_down_sync(0xffffffffu, a2, off);
            a3 += __shfl_down_sync(0xffffffffu, a3, off);
        }
        if (lane == 0) {
            g_dv[k0 + 0] = a0;
            if (nk > 1) g_dv[k0 + 1] = a1;
            if (nk > 2) g_dv[k0 + 2] = a2;
            if (nk > 3) g_dv[k0 + 3] = a3;
            red_release(&g_cdv);
        }
    } else {
        for (int g = warp - 1; g < 4 * nk; g += (NWARP - 1)) {
            const float4* r4 = (const float4*)(sWhh + g * DUNITS);
            const float4* y4 = (const float4*)s_y;
            float a = 0.f;
#pragma unroll
            for (int q = 0; q < 4; q++) {
                float4 w = r4[lane + 32 * q], yv = y4[lane + 32 * q];
                a += w.x * yv.x + w.y * yv.y + w.z * yv.z + w.w * yv.w;
            }
            for (int off = 16; off; off >>= 1)
                a += __shfl_down_sync(0xffffffffu, a, off);
            if (lane == 0) s_gh[g] = a;
        }
    }
    ONE_POLL(g_cdv, NB * e);
    if (tid < JOINT / 4) ((float4*)s_dv)[tid] = __ldcv(((const float4*)g_dv) + tid);
    s_hp[tid] = g_hp[tid];
    s_hp[tid + NT] = g_hp[tid + NT];
    __syncthreads();

    float score = 0.f;

    for (int t = 0; t < T_FRAMES; t++) {
        const int par = t & 1;

        // ===== z fully local: z = tanh(hp_t + dv), 2 elems/thread =====
        s_z[tid]      = tanhf(s_hp[tid]      + s_dv[tid]);
        s_z[tid + NT] = tanhf(s_hp[tid + NT] + s_dv[tid + NT]);
        __syncthreads();

        // z slice into registers (stride-32 cols -> conflict-free scalar LDS)
        float zreg[16];
#pragma unroll
        for (int j = 0; j < 16; j++) zreg[j] = s_z[lane + 32 * j];

        // prefetch next hp row (2 elems/thread)
        float hpn0 = 0.f, hpn1 = 0.f;
        if (t + 1 < T_FRAMES) {
            hpn0 = __ldg(&g_hp[(size_t)(t + 1) * JOINT + tid]);
            hpn1 = __ldg(&g_hp[(size_t)(t + 1) * JOINT + tid + NT]);
        }

        // ===== logits from REGISTERS =====
        float acc[RROWS];
#pragma unroll
        for (int i = 0; i < RROWS; i++) acc[i] = 0.f;
#pragma unroll
        for (int j = 0; j < 16; j++) {
            float zv = zreg[j];
#pragma unroll
            for (int i = 0; i < RROWS; i++) acc[i] += wr[i][j] * zv;
        }
        s_hp[tid] = hpn0; s_hp[tid + NT] = hpn1;
#pragma unroll
        for (int i = 0; i < RROWS; i++) {
            float a = acc[i];
            a += __shfl_down_sync(0xffffffffu, a, 16);
            a += __shfl_down_sync(0xffffffffu, a, 8);
            a += __shfl_down_sync(0xffffffffu, a, 4);
            a += __shfl_down_sync(0xffffffffu, a, 2);
            a += __shfl_down_sync(0xffffffffu, a, 1);
            acc[i] = a;
        }

        // per-warp online softmax stats on lane 0
        if (lane == 0) {
            float m = -INFINITY, s = 0.f;
            int a = 0x7fffffff;
#pragma unroll
            for (int i = 0; i < RROWS; i++) {
                int lr = warp + NWARP * i;
                if (lr < nr) {
                    float l = acc[i] + s_bo[lr];
                    if (l > m) { s = s * __expf(m - l) + 1.f; m = l; a = r0 + lr; }
                    else       { s += __expf(l - m); }
                }
            }
            s_wm[warp] = m; s_wa[warp] = a; s_ws[warp] = s;
        }
        __syncthreads();

        // warp0: block merge (8 warps) + publish partial + release
        if (warp == 0) {
            float mo = (lane < NWARP) ? s_wm[lane] : -INFINITY;
            float so = (lane < NWARP) ? s_ws[lane] : 0.f;
            int   ao = (lane < NWARP) ? s_wa[lane] : 0x7fffffff;
            float m = mo; int a = ao;
#pragma unroll
            for (int off = 4; off; off >>= 1) {
                float m2 = __shfl_xor_sync(0xffffffffu, m, off);
                int   a2 = __shfl_xor_sync(0xffffffffu, a, off);
                if (m2 > m || (m2 == m && a2 < a)) { m = m2; a = a2; }
            }
            m = __shfl_sync(0xffffffffu, m, 0);
            a = __shfl_sync(0xffffffffu, a, 0);
            float sc = (lane < NWARP && mo != -INFINITY) ? so * __expf(mo - m) : 0.f;
#pragma unroll
            for (int off = 4; off; off >>= 1)
                sc += __shfl_xor_sync(0xffffffffu, sc, off);
            if (lane == 0) {
                g_part[par][b] = make_float4(m, sc, __int_as_float(a), 0.f);
                red_release(&g_cp);
            }
        }

        // ===== wait partials (single poller) + gather =====
        ONE_POLL(g_cp, (unsigned)NB * (unsigned)(t + 1));
        if (tid < NB) {
            float4 p = __ldcv(&g_part[par][tid]);
            s_pm[tid] = p.x; s_ps[tid] = p.y; s_pa[tid] = __float_as_int(p.z);
        }
        __syncthreads();

        // parallel global merge: warps 0..4 handle 32 slots each
        if (warp < 5) {
            int idx = warp * 32 + lane;
            bool vld = idx < NB;
            float m = vld ? s_pm[idx] : -INFINITY;
            float s = vld ? s_ps[idx] : 0.f;
            int   a = vld ? s_pa[idx] : 0x7fffffff;
#pragma unroll
            for (int off = 16; off; off >>= 1) {
                float m2 = __shfl_xor_sync(0xffffffffu, m, off);
                float s2 = __shfl_xor_sync(0xffffffffu, s, off);
                int   a2 = __shfl_xor_sync(0xffffffffu, a, off);
                float M  = (m2 > m) ? m2 : m;
                int   A  = (m2 > m || (m2 == m && a2 < a)) ? a2 : a;
                float e1 = (m  == -INFINITY) ? 0.f : __expf(m  - M);
                float e2 = (m2 == -INFINITY) ? 0.f : __expf(m2 - M);
                s = s * e1 + s2 * e2;
                m = M; a = A;
            }
            if (lane == 0) { s_wm[warp] = m; s_wa[warp] = a; s_ws[warp] = s; }
        }
        __syncthreads();
        if (warp == 0) {
            float m = (lane < 5) ? s_wm[lane] : -INFINITY;
            float s = (lane < 5) ? s_ws[lane] : 0.f;
            int   a = (lane < 5) ? s_wa[lane] : 0x7fffffff;
#pragma unroll
            for (int off = 4; off; off >>= 1) {
                float m2 = __shfl_xor_sync(0xffffffffu, m, off);
                float s2 = __shfl_xor_sync(0xffffffffu, s, off);
                int   a2 = __shfl_xor_sync(0xffffffffu, a, off);
                float M  = (m2 > m) ? m2 : m;
                int   A  = (m2 > m || (m2 == m && a2 < a)) ? a2 : a;
                float e1 = (m  == -INFINITY) ? 0.f : __expf(m  - M);
                float e2 = (m2 == -INFINITY) ? 0.f : __expf(m2 - M);
                s = s * e1 + s2 * e2;
                m = M; a = A;
            }
            if (lane == 0) {
                s_bc[0] = __int_as_float(a);
                s_bc[1] = -__logf(s);
            }
        }
        __syncthreads();

        const int   pred    = __float_as_int(s_bc[0]);
        const float logp    = s_bc[1];
        const bool  emitted = (pred != 0);

        if (b == 0 && tid == 0) {
            if (t < out_size) out[t] = emitted ? (float)pred : 0.0f;
            if (emitted) score += logp;
        }

        // ===== emission: LSTM + y handoff + dv/gh refresh =====
        if (emitted) {
            e++;
            s_z[tid]      = __ldg(&embed[(size_t)pred * DUNITS + tid]);       // ey
            s_z[tid + NT] = __ldg(&embed[(size_t)pred * DUNITS + tid + NT]);
            __syncthreads();

            for (int lr = warp; lr < 4 * nk; lr += NWARP) {
                const float4* r4 = (const float4*)(sWih + lr * DUNITS);
                const float4* e4 = (const float4*)s_z;
                float acc2 = 0.f;
#pragma unroll
                for (int q = 0; q < 4; q++) {
                    float4 w = r4[lane + 32 * q], ev = e4[lane + 32 * q];
                    acc2 += w.x * ev.x + w.y * ev.y + w.z * ev.z + w.w * ev.w;
                }
                for (int off = 16; off; off >>= 1)
                    acc2 += __shfl_down_sync(0xffffffffu, acc2, off);
                if (lane == 0) s_gt[lr] = s_bs[lr] + s_gh[lr] + acc2;
            }
            __syncthreads();

            if (warp == 0) {
                if (lane < nk) {
                    float gi_ = s_gt[4 * lane + 0], gf_ = s_gt[4 * lane + 1];
                    float gg_ = s_gt[4 * lane + 2], go_ = s_gt[4 * lane + 3];
                    float c  = s_c[lane];
                    float cn = sigm(gf_) * c + sigm(gi_) * tanhf(gg_);
                    float yn = sigm(go_) * tanhf(cn);
                    s_c[lane] = cn;
                    g_yv[k0 + lane] = yn;
                }
                __syncwarp();
                if (lane == 0) red_release(&g_cy);
            }
            ONE_POLL(g_cy, NB * e);
            if (tid < DUNITS / 4)
                ((float4*)s_y)[tid] = __ldcv(((const float4*)g_yv) + tid);
            __syncthreads();

            // dv interleaved (warp0) + gh refresh (warps 1..7)
            if (warp == 0) {
                const float4* y4 = (const float4*)s_y;
                float a0 = 0.f, a1 = 0.f, a2 = 0.f, a3 = 0.f;
#pragma unroll
                for (int q = 0; q < 4; q++) {
                    float4 yv = y4[lane + 32 * q];
                    float4 w0 = ((const float4*)(sWdec + 0 * DUNITS))[lane + 32 * q];
                    float4 w1 = ((const float4*)(sWdec + 1 * DUNITS))[lane + 32 * q];
                    float4 w2 = ((const float4*)(sWdec + 2 * DUNITS))[lane + 32 * q];
                    float4 w3 = ((const float4*)(sWdec + 3 * DUNITS))[lane + 32 * q];
                    a0 += w0.x * yv.x + w0.y * yv.y + w0.z * yv.z + w0.w * yv.w;
                    a1 += w1.x * yv.x + w1.y * yv.y + w1.z * yv.z + w1.w * yv.w;
                    a2 += w2.x * yv.x + w2.y * yv.y + w2.z * yv.z + w2.w * yv.w;
                    a3 += w3.x * yv.x + w3.y * yv.y + w3.z * yv.z + w3.w * yv.w;
                }
#pragma unroll
                for (int off = 16; off; off >>= 1) {
                    a0 += __shfl_down_sync(0xffffffffu, a0, off);
                    a1 += __shfl_down_sync(0xffffffffu, a1, off);
                    a2 += __shfl_down_sync(0xffffffffu, a2, off);
                    a3 += __shfl_down_sync(0xffffffffu, a3, off);
                }
                if (lane == 0) {
                    g_dv[k0 + 0] = a0;
                    if (nk > 1) g_dv[k0 + 1] = a1;
                    if (nk > 2) g_dv[k0 + 2] = a2;
                    if (nk > 3) g_dv[k0 + 3] = a3;
                    red_release(&g_cdv);
                }
            } else {
                for (int g = warp - 1; g < 4 * nk; g += (NWARP - 1)) {
                    const float4* r4 = (const float4*)(sWhh + g * DUNITS);
                    const float4* y4 = (const float4*)s_y;
                    float a = 0.f;
#pragma unroll
                    for (int q = 0; q < 4; q++) {
                        float4 w = r4[lane + 32 * q], yv = y4[lane + 32 * q];
                        a += w.x * yv.x + w.y * yv.y + w.z * yv.z + w.w * yv.w;
                    }
                    for (int off = 16; off; off >>= 1)
                        a += __shfl_down_sync(0xffffffffu, a, off);
                    if (lane == 0) s_gh[g] = a;
                }
            }
            ONE_POLL(g_cdv, NB * e);
            if (tid < JOINT / 4)
                ((float4*)s_dv)[tid] = __ldcv(((const float4*)g_dv) + tid);
            __syncthreads();
        }
    }

    if (b == 0) {
        if (tid == 0 && out_size > T_FRAMES) out[T_FRAMES] = score;
        for (int i = T_FRAMES + 1 + tid; i < out_size; i += NT) out[i] = 0.f;
    }
}

// ---------------- launch ----------------
extern "C" void kernel_launch(void* const* d_in, const int* in_sizes, int n_in,
                              void* d_out, int out_size) {
    (void)in_sizes; (void)n_in;
    const float* h     = (const float*)d_in[0];
    const float* embed = (const float*)d_in[1];
    const float* Wih   = (const float*)d_in[2];
    const float* Whh   = (const float*)d_in[3];
    const float* bih   = (const float*)d_in[4];
    const float* bhh   = (const float*)d_in[5];
    const float* Wenc  = (const float*)d_in[6];
    const float* benc  = (const float*)d_in[7];
    const float* Wdec  = (const float*)d_in[8];
    const float* Wout  = (const float*)d_in[9];
    const float* bout  = (const float*)d_in[10];
    float* out = (float*)d_out;

    const int smem_bytes = SM_TOTAL_FLOATS * (int)sizeof(float);
    cudaFuncSetAttribute(decode_kernel,
                         cudaFuncAttributeMaxDynamicSharedMemorySize, smem_bytes);

    hp_kernel<<<T_FRAMES / 8, 256>>>(h, Wenc, benc);
    decode_kernel<<<NB, NT, smem_bytes>>>(embed, Wih, Whh, bih, bhh,
                                          Wdec, Wout, bout, out, out_size);
}